// round 1
// baseline (speedup 1.0000x reference)
#include <cuda_runtime.h>
#include <math.h>

#define NPTS 1024
#define TLEN 64
#define CDIM 256

// Scratch: __device__ globals (no allocation allowed in kernel_launch).
__device__ float  g_xm[2][NPTS * CDIM];     // time-means (x, y)
__device__ float  g_norm[2][NPTS];          // row squared norms
__device__ float  g_d[2][NPTS * NPTS];      // distance matrices (4 MB each)
__device__ float  g_rs[2][NPTS];            // row sums of d
__device__ double g_tot[2];                 // total sums of d
__device__ double g_acc[3];                 // sum(a*b), sum(a*a), sum(b*b)

__global__ void init_kernel() {
    g_tot[0] = 0.0; g_tot[1] = 0.0;
    g_acc[0] = 0.0; g_acc[1] = 0.0; g_acc[2] = 0.0;
}

// ---------------------------------------------------------------------------
// Kernel 1: time-mean over T plus per-row squared norm.
// grid (1024, 2), block 256. Each thread owns one channel c; 64 strided,
// fully-coalesced loads; unrolled for MLP.
// ---------------------------------------------------------------------------
__global__ void mean_norm_kernel(const float* __restrict__ a,
                                 const float* __restrict__ b) {
    const int n = blockIdx.x;
    const int w = blockIdx.y;
    const float* __restrict__ src = (w == 0) ? a : b;
    const int c = threadIdx.x;

    const float* p = src + (size_t)n * (TLEN * CDIM) + c;
    float s = 0.f;
#pragma unroll
    for (int t = 0; t < TLEN; ++t) s += p[(size_t)t * CDIM];
    const float m = s * (1.0f / TLEN);
    g_xm[w][n * CDIM + c] = m;

    // block-reduce sum of m*m -> row norm
    float sq = m * m;
    __shared__ float red[8];
#pragma unroll
    for (int off = 16; off > 0; off >>= 1)
        sq += __shfl_down_sync(0xffffffffu, sq, off);
    const int lane = c & 31, wid = c >> 5;
    if (lane == 0) red[wid] = sq;
    __syncthreads();
    if (wid == 0) {
        float v = (lane < 8) ? red[lane] : 0.f;
#pragma unroll
        for (int off = 4; off > 0; off >>= 1)
            v += __shfl_down_sync(0xffffffffu, v, off);
        if (lane == 0) g_norm[w][n] = v;
    }
}

// ---------------------------------------------------------------------------
// Kernel 2: Gram-based pairwise distance.
// d_ij = sqrt(max(||xi||^2 + ||xj||^2 - 2 xi.xj, 0) + 1e-12)
// 64x64 output tiles, K-chunks of 32, 4x4 register micro-tile per thread.
// Symmetry: only tiles with bx <= by compute; both halves written.
// grid (16, 16, 2), block 256.
// ---------------------------------------------------------------------------
__global__ void gemm_dist_kernel() {
    const int bx = blockIdx.x, by = blockIdx.y, w = blockIdx.z;
    if (bx > by) return;   // upper-triangle tiles only
    const float* __restrict__ X = g_xm[w];
    const int I = bx * 64, J = by * 64;

    __shared__ float As[32][68];  // [k][m], pad 68 keeps f4 LDS aligned, spreads STS banks
    __shared__ float Bs[32][68];

    const int tid = threadIdx.x;
    const int tx = tid & 15, ty = tid >> 4;

    float acc[4][4];
#pragma unroll
    for (int i = 0; i < 4; ++i)
#pragma unroll
        for (int j = 0; j < 4; ++j) acc[i][j] = 0.f;

    for (int k0 = 0; k0 < CDIM; k0 += 32) {
        __syncthreads();
#pragma unroll
        for (int r = 0; r < 2; ++r) {
            const int m  = (tid >> 3) + 32 * r;
            const int kk = (tid & 7) * 4;
            float4 va = *(const float4*)(X + (size_t)(I + m) * CDIM + k0 + kk);
            As[kk + 0][m] = va.x; As[kk + 1][m] = va.y;
            As[kk + 2][m] = va.z; As[kk + 3][m] = va.w;
            float4 vb = *(const float4*)(X + (size_t)(J + m) * CDIM + k0 + kk);
            Bs[kk + 0][m] = vb.x; Bs[kk + 1][m] = vb.y;
            Bs[kk + 2][m] = vb.z; Bs[kk + 3][m] = vb.w;
        }
        __syncthreads();
#pragma unroll
        for (int k = 0; k < 32; ++k) {
            const float4 a4 = *(const float4*)&As[k][ty * 4];
            const float4 b4 = *(const float4*)&Bs[k][tx * 4];
            const float av[4] = {a4.x, a4.y, a4.z, a4.w};
            const float bv[4] = {b4.x, b4.y, b4.z, b4.w};
#pragma unroll
            for (int i = 0; i < 4; ++i)
#pragma unroll
                for (int j = 0; j < 4; ++j)
                    acc[i][j] = fmaf(av[i], bv[j], acc[i][j]);
        }
    }

    float nI[4], nJ[4];
#pragma unroll
    for (int i = 0; i < 4; ++i) nI[i] = g_norm[w][I + ty * 4 + i];
#pragma unroll
    for (int j = 0; j < 4; ++j) nJ[j] = g_norm[w][J + tx * 4 + j];

    float* __restrict__ D = g_d[w];
#pragma unroll
    for (int i = 0; i < 4; ++i) {
        const int gi = I + ty * 4 + i;
#pragma unroll
        for (int j = 0; j < 4; ++j) {
            const int gj = J + tx * 4 + j;
            const float s = nI[i] + nJ[j] - 2.f * acc[i][j];
            const float d = sqrtf(fmaxf(s, 0.f) + 1e-12f);
            D[(size_t)gi * NPTS + gj] = d;
            D[(size_t)gj * NPTS + gi] = d;
        }
    }
}

// ---------------------------------------------------------------------------
// Kernel 3: row sums + total sum of each d matrix. grid (1024, 2), block 256.
// ---------------------------------------------------------------------------
__global__ void rowsum_kernel() {
    const int i = blockIdx.x, w = blockIdx.y;
    const float* __restrict__ D = g_d[w] + (size_t)i * NPTS;
    const int t = threadIdx.x;
    float s = D[t] + D[t + 256] + D[t + 512] + D[t + 768];

    __shared__ float red[8];
#pragma unroll
    for (int off = 16; off > 0; off >>= 1)
        s += __shfl_down_sync(0xffffffffu, s, off);
    const int lane = t & 31, wid = t >> 5;
    if (lane == 0) red[wid] = s;
    __syncthreads();
    if (wid == 0) {
        float v = (lane < 8) ? red[lane] : 0.f;
#pragma unroll
        for (int off = 4; off > 0; off >>= 1)
            v += __shfl_down_sync(0xffffffffu, v, off);
        if (lane == 0) {
            g_rs[w][i] = v;
            atomicAdd(&g_tot[w], (double)v);
        }
    }
}

// ---------------------------------------------------------------------------
// Kernel 4: double-centered products. a_ij = d_ij - rm_i - rm_j + tm
// (d symmetric so row-mean == col-mean). Accumulate sum(ab), sum(aa),
// sum(bb) per block, fold into double accumulators.
// grid 1024, block 256.
// ---------------------------------------------------------------------------
__global__ void prod_kernel() {
    const int i = blockIdx.x;
    const int t = threadIdx.x;
    const float invN  = 1.0f / NPTS;
    const float invN2 = 1.0f / ((float)NPTS * (float)NPTS);

    const float tmx = (float)g_tot[0] * invN2;
    const float tmy = (float)g_tot[1] * invN2;
    const float basex = tmx - g_rs[0][i] * invN;
    const float basey = tmy - g_rs[1][i] * invN;

    const float* __restrict__ Dx = g_d[0] + (size_t)i * NPTS;
    const float* __restrict__ Dy = g_d[1] + (size_t)i * NPTS;

    float pxy = 0.f, pxx = 0.f, pyy = 0.f;
#pragma unroll
    for (int jj = 0; jj < 4; ++jj) {
        const int j = t + jj * 256;
        const float a = Dx[j] - g_rs[0][j] * invN + basex;
        const float b = Dy[j] - g_rs[1][j] * invN + basey;
        pxy = fmaf(a, b, pxy);
        pxx = fmaf(a, a, pxx);
        pyy = fmaf(b, b, pyy);
    }

    __shared__ float r0[8], r1[8], r2[8];
#pragma unroll
    for (int off = 16; off > 0; off >>= 1) {
        pxy += __shfl_down_sync(0xffffffffu, pxy, off);
        pxx += __shfl_down_sync(0xffffffffu, pxx, off);
        pyy += __shfl_down_sync(0xffffffffu, pyy, off);
    }
    const int lane = t & 31, wid = t >> 5;
    if (lane == 0) { r0[wid] = pxy; r1[wid] = pxx; r2[wid] = pyy; }
    __syncthreads();
    if (wid == 0) {
        float v0 = (lane < 8) ? r0[lane] : 0.f;
        float v1 = (lane < 8) ? r1[lane] : 0.f;
        float v2 = (lane < 8) ? r2[lane] : 0.f;
#pragma unroll
        for (int off = 4; off > 0; off >>= 1) {
            v0 += __shfl_down_sync(0xffffffffu, v0, off);
            v1 += __shfl_down_sync(0xffffffffu, v1, off);
            v2 += __shfl_down_sync(0xffffffffu, v2, off);
        }
        if (lane == 0) {
            atomicAdd(&g_acc[0], (double)v0);
            atomicAdd(&g_acc[1], (double)v1);
            atomicAdd(&g_acc[2], (double)v2);
        }
    }
}

// ---------------------------------------------------------------------------
// Kernel 5: scalar finalize (double precision).
// ---------------------------------------------------------------------------
__global__ void finalize_kernel(float* __restrict__ out) {
    const double inv = 1.0 / ((double)NPTS * (double)NPTS);
    const double mxy = g_acc[0] * inv;
    const double mxx = g_acc[1] * inv;
    const double myy = g_acc[2] * inv;
    const double r = mxy / sqrt(mxx * myy + 1e-9);
    out[0] = (float)(1.0 - r);
}

extern "C" void kernel_launch(void* const* d_in, const int* in_sizes, int n_in,
                              void* d_out, int out_size) {
    const float* a = (const float*)d_in[0];  // output_1 (1024,64,256) f32
    const float* b = (const float*)d_in[1];  // feature  (1024,64,256) f32
    // d_in[2] = mask, unused by the reference module.

    init_kernel<<<1, 1>>>();
    mean_norm_kernel<<<dim3(NPTS, 2), 256>>>(a, b);
    gemm_dist_kernel<<<dim3(16, 16, 2), 256>>>();
    rowsum_kernel<<<dim3(NPTS, 2), 256>>>();
    prod_kernel<<<NPTS, 256>>>();
    finalize_kernel<<<1, 1>>>((float*)d_out);
}

// round 2
// speedup vs baseline: 1.2623x; 1.2623x over previous
#include <cuda_runtime.h>
#include <math.h>

#define NPTS 1024
#define TLEN 64
#define CDIM 256

typedef unsigned long long ull;

// Scratch (__device__ globals — no allocation allowed).
__device__ float  g_xm[2][NPTS * CDIM];     // time-means (x, y)
__device__ float  g_norm[2][NPTS];          // row squared norms
__device__ float  g_d[2][NPTS * NPTS];      // distance matrices (4 MB each)
__device__ float  g_rs[2][NPTS];            // row sums of d (atomic-accumulated)
__device__ double g_tot[2];                 // total sums of d
__device__ double g_acc[3];                 // sum(a*b), sum(a*a), sum(b*b)

// ---- packed f32x2 helpers (FFMA2 — ptxas won't emit this from C++) ----
__device__ __forceinline__ void ffma2(ull& c, ull a, ull b) {
    asm("fma.rn.f32x2 %0, %1, %2, %0;" : "+l"(c) : "l"(a), "l"(b));
}
__device__ __forceinline__ ull dup2(float v) {
    ull r;
    asm("mov.b64 %0, {%1, %1};" : "=l"(r) : "f"(v));
    return r;
}
__device__ __forceinline__ float2 unpack2(ull v) {
    float2 r;
    asm("mov.b64 {%0, %1}, %2;" : "=f"(r.x), "=f"(r.y) : "l"(v));
    return r;
}

__global__ void init_kernel() {
    const int t = threadIdx.x;
    if (t == 0) {
        g_tot[0] = 0.0; g_tot[1] = 0.0;
        g_acc[0] = 0.0; g_acc[1] = 0.0; g_acc[2] = 0.0;
    }
#pragma unroll
    for (int r = 0; r < 4; ++r) {
        g_rs[0][t + 256 * r] = 0.f;
        g_rs[1][t + 256 * r] = 0.f;
    }
}

// ---------------------------------------------------------------------------
// Kernel 1: time-mean over T + per-row squared norm. float4 loads.
// grid (256, 2), block 256: each block handles 4 rows; 64 threads per row,
// each thread owns 4 channels (one float4), 64 fully-coalesced LDG.128.
// ---------------------------------------------------------------------------
__global__ void mean_norm_kernel(const float* __restrict__ a,
                                 const float* __restrict__ b) {
    const int w = blockIdx.y;
    const float* __restrict__ src = (w == 0) ? a : b;
    const int tid = threadIdx.x;
    const int sub = tid >> 6;          // 0..3 : which row of the 4
    const int c4  = tid & 63;          // float4 slot within the row
    const int n   = blockIdx.x * 4 + sub;

    const float4* __restrict__ p =
        (const float4*)(src + (size_t)n * (TLEN * CDIM)) + c4;
    float4 s = make_float4(0.f, 0.f, 0.f, 0.f);
#pragma unroll
    for (int t = 0; t < TLEN; ++t) {
        float4 v = p[(size_t)t * (CDIM / 4)];
        s.x += v.x; s.y += v.y; s.z += v.z; s.w += v.w;
    }
    const float inv = 1.0f / TLEN;
    s.x *= inv; s.y *= inv; s.z *= inv; s.w *= inv;
    ((float4*)(g_xm[w] + (size_t)n * CDIM))[c4] = s;

    float sq = s.x * s.x + s.y * s.y + s.z * s.z + s.w * s.w;
#pragma unroll
    for (int off = 16; off > 0; off >>= 1)
        sq += __shfl_down_sync(0xffffffffu, sq, off);

    __shared__ float part[8];
    if ((tid & 31) == 0) part[tid >> 5] = sq;
    __syncthreads();
    if (tid < 4) g_norm[w][blockIdx.x * 4 + tid] = part[2 * tid] + part[2 * tid + 1];
}

// ---------------------------------------------------------------------------
// Kernel 2: Gram-based pairwise distance with fused row sums / total sum.
// d_ij = sqrt(max(||xi||^2+||xj||^2-2 xi.xj, 0) + 1e-12)
// 64x64 tile, 128 threads, 8x4 micro-tile with f32x2 packed FMAs
// (accumulators paired along i so A-pairs load natively from [k][m] shared).
// Full grid (16,16,2): every tile computed -> row sums are simple, stores
// are fully coalesced, no transposed scatter.
// ---------------------------------------------------------------------------
__global__ void __launch_bounds__(128) gemm_dist_fused_kernel() {
    const int bx = blockIdx.x, by = blockIdx.y, w = blockIdx.z;
    const float* __restrict__ X = g_xm[w];
    const int I = by * 64;   // output rows
    const int J = bx * 64;   // output cols

    __shared__ __align__(16) float As[32][68];  // [k][m] rows of I-block
    __shared__ __align__(16) float Bs[32][68];  // [k][m] rows of J-block
    __shared__ float sh_rs[64];
    __shared__ float tp[2];

    const int tid = threadIdx.x;    // 0..127
    const int tx = tid & 15;        // j group: 4 cols
    const int ty = tid >> 4;        // i group: 8 rows

    ull acc[4][4];                  // [i-pair][j]
#pragma unroll
    for (int ip = 0; ip < 4; ++ip)
#pragma unroll
        for (int j = 0; j < 4; ++j) acc[ip][j] = 0ull;

    for (int k0 = 0; k0 < CDIM; k0 += 32) {
        __syncthreads();
#pragma unroll
        for (int r = 0; r < 4; ++r) {
            const int m  = (tid >> 3) + 16 * r;        // 0..63
            const int kk = (tid & 7) * 4;              // 0..28
            float4 va = *(const float4*)(X + (size_t)(I + m) * CDIM + k0 + kk);
            As[kk + 0][m] = va.x; As[kk + 1][m] = va.y;
            As[kk + 2][m] = va.z; As[kk + 3][m] = va.w;
            float4 vb = *(const float4*)(X + (size_t)(J + m) * CDIM + k0 + kk);
            Bs[kk + 0][m] = vb.x; Bs[kk + 1][m] = vb.y;
            Bs[kk + 2][m] = vb.z; Bs[kk + 3][m] = vb.w;
        }
        __syncthreads();
#pragma unroll
        for (int k = 0; k < 32; ++k) {
            ulonglong2 a01 = *(const ulonglong2*)&As[k][ty * 8];
            ulonglong2 a23 = *(const ulonglong2*)&As[k][ty * 8 + 4];
            const ull ap[4] = {a01.x, a01.y, a23.x, a23.y};
            float4 b4 = *(const float4*)&Bs[k][tx * 4];
            const ull bd[4] = {dup2(b4.x), dup2(b4.y), dup2(b4.z), dup2(b4.w)};
#pragma unroll
            for (int ip = 0; ip < 4; ++ip)
#pragma unroll
                for (int j = 0; j < 4; ++j)
                    ffma2(acc[ip][j], ap[ip], bd[j]);
        }
    }

    // Epilogue: distances, coalesced stores, per-row sums.
    float nI[8], nJ[4];
#pragma unroll
    for (int i = 0; i < 8; ++i) nI[i] = g_norm[w][I + ty * 8 + i];
#pragma unroll
    for (int j = 0; j < 4; ++j) nJ[j] = g_norm[w][J + tx * 4 + j];

    float* __restrict__ D = g_d[w];
#pragma unroll
    for (int ip = 0; ip < 4; ++ip) {
        const float2 c0 = unpack2(acc[ip][0]);
        const float2 c1 = unpack2(acc[ip][1]);
        const float2 c2 = unpack2(acc[ip][2]);
        const float2 c3 = unpack2(acc[ip][3]);
#pragma unroll
        for (int h = 0; h < 2; ++h) {
            const int i = 2 * ip + h;
            const float ni = nI[i];
            const float d0x = h ? c0.y : c0.x;
            const float d1x = h ? c1.y : c1.x;
            const float d2x = h ? c2.y : c2.x;
            const float d3x = h ? c3.y : c3.x;
            float4 dv;
            dv.x = sqrtf(fmaxf(ni + nJ[0] - 2.f * d0x, 0.f) + 1e-12f);
            dv.y = sqrtf(fmaxf(ni + nJ[1] - 2.f * d1x, 0.f) + 1e-12f);
            dv.z = sqrtf(fmaxf(ni + nJ[2] - 2.f * d2x, 0.f) + 1e-12f);
            dv.w = sqrtf(fmaxf(ni + nJ[3] - 2.f * d3x, 0.f) + 1e-12f);
            *(float4*)(D + (size_t)(I + ty * 8 + i) * NPTS + J + tx * 4) = dv;

            float rsum = dv.x + dv.y + dv.z + dv.w;
#pragma unroll
            for (int off = 8; off > 0; off >>= 1)
                rsum += __shfl_down_sync(0xffffffffu, rsum, off, 16);
            if (tx == 0) sh_rs[ty * 8 + i] = rsum;   // unique writer per (ty,i)
        }
    }
    __syncthreads();
    if (tid < 64) {
        float v = sh_rs[tid];
        atomicAdd(&g_rs[w][I + tid], v);
#pragma unroll
        for (int off = 16; off > 0; off >>= 1)
            v += __shfl_down_sync(0xffffffffu, v, off);
        if ((tid & 31) == 0) tp[tid >> 5] = v;
    }
    __syncthreads();
    if (tid == 0) atomicAdd(&g_tot[w], (double)(tp[0] + tp[1]));
}

// ---------------------------------------------------------------------------
// Kernel 3: double-centered products, single float4 pass.
// a_ij = d_ij - rs_i/N - rs_j/N + tot/N^2. grid 1024, block 256.
// ---------------------------------------------------------------------------
__global__ void prod_kernel() {
    const int i = blockIdx.x;
    const int t = threadIdx.x;
    const float invN  = 1.0f / NPTS;
    const double invN2 = 1.0 / ((double)NPTS * (double)NPTS);

    const float tmx = (float)(g_tot[0] * invN2);
    const float tmy = (float)(g_tot[1] * invN2);
    const float basex = tmx - g_rs[0][i] * invN;
    const float basey = tmy - g_rs[1][i] * invN;

    const float4 dx = ((const float4*)(g_d[0] + (size_t)i * NPTS))[t];
    const float4 dy = ((const float4*)(g_d[1] + (size_t)i * NPTS))[t];
    const float4 r0 = ((const float4*)g_rs[0])[t];
    const float4 r1 = ((const float4*)g_rs[1])[t];

    float4 av, bv;
    av.x = dx.x - r0.x * invN + basex;  bv.x = dy.x - r1.x * invN + basey;
    av.y = dx.y - r0.y * invN + basex;  bv.y = dy.y - r1.y * invN + basey;
    av.z = dx.z - r0.z * invN + basex;  bv.z = dy.z - r1.z * invN + basey;
    av.w = dx.w - r0.w * invN + basex;  bv.w = dy.w - r1.w * invN + basey;

    float pxy = av.x*bv.x + av.y*bv.y + av.z*bv.z + av.w*bv.w;
    float pxx = av.x*av.x + av.y*av.y + av.z*av.z + av.w*av.w;
    float pyy = bv.x*bv.x + bv.y*bv.y + bv.z*bv.z + bv.w*bv.w;

    __shared__ float s0[8], s1[8], s2[8];
#pragma unroll
    for (int off = 16; off > 0; off >>= 1) {
        pxy += __shfl_down_sync(0xffffffffu, pxy, off);
        pxx += __shfl_down_sync(0xffffffffu, pxx, off);
        pyy += __shfl_down_sync(0xffffffffu, pyy, off);
    }
    const int lane = t & 31, wid = t >> 5;
    if (lane == 0) { s0[wid] = pxy; s1[wid] = pxx; s2[wid] = pyy; }
    __syncthreads();
    if (wid == 0) {
        float v0 = (lane < 8) ? s0[lane] : 0.f;
        float v1 = (lane < 8) ? s1[lane] : 0.f;
        float v2 = (lane < 8) ? s2[lane] : 0.f;
#pragma unroll
        for (int off = 4; off > 0; off >>= 1) {
            v0 += __shfl_down_sync(0xffffffffu, v0, off);
            v1 += __shfl_down_sync(0xffffffffu, v1, off);
            v2 += __shfl_down_sync(0xffffffffu, v2, off);
        }
        if (lane == 0) {
            atomicAdd(&g_acc[0], (double)v0);
            atomicAdd(&g_acc[1], (double)v1);
            atomicAdd(&g_acc[2], (double)v2);
        }
    }
}

__global__ void finalize_kernel(float* __restrict__ out) {
    const double inv = 1.0 / ((double)NPTS * (double)NPTS);
    const double mxy = g_acc[0] * inv;
    const double mxx = g_acc[1] * inv;
    const double myy = g_acc[2] * inv;
    const double r = mxy / sqrt(mxx * myy + 1e-9);
    out[0] = (float)(1.0 - r);
}

extern "C" void kernel_launch(void* const* d_in, const int* in_sizes, int n_in,
                              void* d_out, int out_size) {
    const float* a = (const float*)d_in[0];  // output_1 (1024,64,256) f32
    const float* b = (const float*)d_in[1];  // feature  (1024,64,256) f32
    // d_in[2] = mask, unused by the reference module.

    init_kernel<<<1, 256>>>();
    mean_norm_kernel<<<dim3(NPTS / 4, 2), 256>>>(a, b);
    gemm_dist_fused_kernel<<<dim3(16, 16, 2), 128>>>();
    prod_kernel<<<NPTS, 256>>>();
    finalize_kernel<<<1, 1>>>((float*)d_out);
}

// round 3
// speedup vs baseline: 1.4718x; 1.1660x over previous
#include <cuda_runtime.h>
#include <math.h>

#define NPTS 1024
#define TLEN 64
#define CDIM 256
#define NTILE 16                 // 1024 / 64
#define NBLK (NTILE * (NTILE + 1) / 2)   // 136 triangular tiles

typedef unsigned long long ull;

// Scratch (__device__ globals — no allocation allowed).
__device__ float  g_xm[2][NPTS * CDIM];  // time-means (x, y)
__device__ float  g_norm[2][NPTS];       // row squared norms
__device__ float  g_rs[2][NPTS];         // row sums of d (atomic-accumulated)
__device__ double g_acc[3];              // sum(dx*dy), sum(dx*dx), sum(dy*dy)

// ---- packed f32x2 helpers (FFMA2 — ptxas won't emit from C++) ----
__device__ __forceinline__ void ffma2(ull& c, ull a, ull b) {
    asm("fma.rn.f32x2 %0, %1, %2, %0;" : "+l"(c) : "l"(a), "l"(b));
}
__device__ __forceinline__ ull dup2(float v) {
    ull r;
    asm("mov.b64 %0, {%1, %1};" : "=l"(r) : "f"(v));
    return r;
}
__device__ __forceinline__ float2 unpack2(ull v) {
    float2 r;
    asm("mov.b64 {%0, %1}, %2;" : "=f"(r.x), "=f"(r.y) : "l"(v));
    return r;
}

// ---------------------------------------------------------------------------
// Kernel 1: time-mean over T + per-row squared norm. Also zero-inits the
// accumulators (block 0 of each w). grid (256, 2), block 256.
// ---------------------------------------------------------------------------
__global__ void mean_norm_kernel(const float* __restrict__ a,
                                 const float* __restrict__ b) {
    const int w = blockIdx.y;
    const float* __restrict__ src = (w == 0) ? a : b;
    const int tid = threadIdx.x;

    if (blockIdx.x == 0) {   // fold init: zero row-sum vectors + scalar accs
#pragma unroll
        for (int r = 0; r < 4; ++r) g_rs[w][tid + 256 * r] = 0.f;
        if (w == 0 && tid == 0) { g_acc[0] = 0.0; g_acc[1] = 0.0; g_acc[2] = 0.0; }
    }

    const int sub = tid >> 6;          // which of the 4 rows
    const int c4  = tid & 63;          // float4 slot within the row
    const int n   = blockIdx.x * 4 + sub;

    const float4* __restrict__ p =
        (const float4*)(src + (size_t)n * (TLEN * CDIM)) + c4;
    float4 s = make_float4(0.f, 0.f, 0.f, 0.f);
#pragma unroll
    for (int t = 0; t < TLEN; ++t) {
        float4 v = p[(size_t)t * (CDIM / 4)];
        s.x += v.x; s.y += v.y; s.z += v.z; s.w += v.w;
    }
    const float inv = 1.0f / TLEN;
    s.x *= inv; s.y *= inv; s.z *= inv; s.w *= inv;
    ((float4*)(g_xm[w] + (size_t)n * CDIM))[c4] = s;

    float sq = s.x * s.x + s.y * s.y + s.z * s.z + s.w * s.w;
#pragma unroll
    for (int off = 16; off > 0; off >>= 1)
        sq += __shfl_down_sync(0xffffffffu, sq, off);

    __shared__ float part[8];
    if ((tid & 31) == 0) part[tid >> 5] = sq;
    __syncthreads();
    if (tid < 4) g_norm[w][blockIdx.x * 4 + tid] = part[2 * tid] + part[2 * tid + 1];
}

// ---------------------------------------------------------------------------
// Kernel 2: triangular pairwise-distance GEMM, fully fused statistics.
// For tile (I<=J) computes dx_ij, dy_ij (both matrices) in registers only:
//   - accumulates sum(dx*dy), sum(dx^2), sum(dy^2)  (x2 for off-diagonal)
//   - row sums into g_rs rows I.. , col sums into rows J.. (symmetry)
// d matrices are NEVER written to memory.
// grid NBLK=136 (single wave), block 128, 8x4 micro-tile, f32x2 FMAs.
// ---------------------------------------------------------------------------
__global__ void __launch_bounds__(128) gemm_dist_fused_kernel() {
    // triangular decode: blockIdx.x -> (bx <= by)
    const int t = blockIdx.x;
    int by = (int)((__fsqrt_rn(8.f * (float)t + 1.f) - 1.f) * 0.5f);
    while ((by + 1) * (by + 2) / 2 <= t) ++by;
    while (by * (by + 1) / 2 > t) --by;
    const int bx = t - by * (by + 1) / 2;
    const bool diag = (bx == by);
    const int I = bx * 64;   // rows
    const int J = by * 64;   // cols

    const float* __restrict__ Xx = g_xm[0];
    const float* __restrict__ Xy = g_xm[1];

    __shared__ __align__(16) float Ax[32][68], Ay[32][68];  // [k][m] rows I-block
    __shared__ __align__(16) float Bx[32][68], By[32][68];  // [k][m] rows J-block
    __shared__ float sh_rsx[64], sh_rsy[64];
    __shared__ float sh_csx[64], sh_csy[64];
    __shared__ float sh_p[3][4];

    const int tid = threadIdx.x;    // 0..127
    const int tx = tid & 15;        // j group (4 cols)
    const int ty = tid >> 4;        // i group (8 rows)

    if (tid < 64) { sh_csx[tid] = 0.f; sh_csy[tid] = 0.f; }

    ull accx[4][4], accy[4][4];     // [i-pair][j]
#pragma unroll
    for (int ip = 0; ip < 4; ++ip)
#pragma unroll
        for (int j = 0; j < 4; ++j) { accx[ip][j] = 0ull; accy[ip][j] = 0ull; }

    const int mm = (tid >> 3);          // 0..15 base row
    const int kk = (tid & 7) * 4;       // k offset 0..28

    float4 vax[4], vay[4], vbx[4], vby[4];
    // prefetch chunk 0
#pragma unroll
    for (int r = 0; r < 4; ++r) {
        const int m = mm + 16 * r;
        vax[r] = *(const float4*)(Xx + (size_t)(I + m) * CDIM + kk);
        vay[r] = *(const float4*)(Xy + (size_t)(I + m) * CDIM + kk);
        vbx[r] = *(const float4*)(Xx + (size_t)(J + m) * CDIM + kk);
        vby[r] = *(const float4*)(Xy + (size_t)(J + m) * CDIM + kk);
    }

    for (int c = 0; c < 8; ++c) {
        __syncthreads();
#pragma unroll
        for (int r = 0; r < 4; ++r) {
            const int m = mm + 16 * r;
            Ax[kk + 0][m] = vax[r].x; Ax[kk + 1][m] = vax[r].y;
            Ax[kk + 2][m] = vax[r].z; Ax[kk + 3][m] = vax[r].w;
            Ay[kk + 0][m] = vay[r].x; Ay[kk + 1][m] = vay[r].y;
            Ay[kk + 2][m] = vay[r].z; Ay[kk + 3][m] = vay[r].w;
            Bx[kk + 0][m] = vbx[r].x; Bx[kk + 1][m] = vbx[r].y;
            Bx[kk + 2][m] = vbx[r].z; Bx[kk + 3][m] = vbx[r].w;
            By[kk + 0][m] = vby[r].x; By[kk + 1][m] = vby[r].y;
            By[kk + 2][m] = vby[r].z; By[kk + 3][m] = vby[r].w;
        }
        __syncthreads();
        if (c < 7) {
            const int k0 = (c + 1) * 32;
#pragma unroll
            for (int r = 0; r < 4; ++r) {
                const int m = mm + 16 * r;
                vax[r] = *(const float4*)(Xx + (size_t)(I + m) * CDIM + k0 + kk);
                vay[r] = *(const float4*)(Xy + (size_t)(I + m) * CDIM + k0 + kk);
                vbx[r] = *(const float4*)(Xx + (size_t)(J + m) * CDIM + k0 + kk);
                vby[r] = *(const float4*)(Xy + (size_t)(J + m) * CDIM + k0 + kk);
            }
        }
#pragma unroll
        for (int k = 0; k < 32; ++k) {
            {
                ulonglong2 a0 = *(const ulonglong2*)&Ax[k][ty * 8];
                ulonglong2 a1 = *(const ulonglong2*)&Ax[k][ty * 8 + 4];
                float4 b4 = *(const float4*)&Bx[k][tx * 4];
                const ull ap[4] = {a0.x, a0.y, a1.x, a1.y};
                const ull bd[4] = {dup2(b4.x), dup2(b4.y), dup2(b4.z), dup2(b4.w)};
#pragma unroll
                for (int ip = 0; ip < 4; ++ip)
#pragma unroll
                    for (int j = 0; j < 4; ++j)
                        ffma2(accx[ip][j], ap[ip], bd[j]);
            }
            {
                ulonglong2 a0 = *(const ulonglong2*)&Ay[k][ty * 8];
                ulonglong2 a1 = *(const ulonglong2*)&Ay[k][ty * 8 + 4];
                float4 b4 = *(const float4*)&By[k][tx * 4];
                const ull ap[4] = {a0.x, a0.y, a1.x, a1.y};
                const ull bd[4] = {dup2(b4.x), dup2(b4.y), dup2(b4.z), dup2(b4.w)};
#pragma unroll
                for (int ip = 0; ip < 4; ++ip)
#pragma unroll
                    for (int j = 0; j < 4; ++j)
                        ffma2(accy[ip][j], ap[ip], bd[j]);
            }
        }
    }

    // -------- Epilogue: distances in registers, fused statistics --------
    float nIx[8], nIy[8], nJx[4], nJy[4];
#pragma unroll
    for (int i = 0; i < 8; ++i) {
        nIx[i] = g_norm[0][I + ty * 8 + i];
        nIy[i] = g_norm[1][I + ty * 8 + i];
    }
#pragma unroll
    for (int j = 0; j < 4; ++j) {
        nJx[j] = g_norm[0][J + tx * 4 + j];
        nJy[j] = g_norm[1][J + tx * 4 + j];
    }

    float pxy = 0.f, pxx = 0.f, pyy = 0.f;
    float rowx[8], rowy[8], colx[4] = {0, 0, 0, 0}, coly[4] = {0, 0, 0, 0};

#pragma unroll
    for (int ip = 0; ip < 4; ++ip) {
        float2 cx[4], cy[4];
#pragma unroll
        for (int j = 0; j < 4; ++j) { cx[j] = unpack2(accx[ip][j]); cy[j] = unpack2(accy[ip][j]); }
#pragma unroll
        for (int h = 0; h < 2; ++h) {
            const int i = 2 * ip + h;
            float rx = 0.f, ry = 0.f;
#pragma unroll
            for (int j = 0; j < 4; ++j) {
                const float gx = h ? cx[j].y : cx[j].x;
                const float gy = h ? cy[j].y : cy[j].x;
                const float dx = sqrtf(fmaxf(nIx[i] + nJx[j] - 2.f * gx, 0.f) + 1e-12f);
                const float dy = sqrtf(fmaxf(nIy[i] + nJy[j] - 2.f * gy, 0.f) + 1e-12f);
                pxy = fmaf(dx, dy, pxy);
                pxx = fmaf(dx, dx, pxx);
                pyy = fmaf(dy, dy, pyy);
                rx += dx; ry += dy;
                colx[j] += dx; coly[j] += dy;
            }
            rowx[i] = rx; rowy[i] = ry;
        }
    }

    // row sums: reduce across tx (16 lanes, same ty)
#pragma unroll
    for (int i = 0; i < 8; ++i) {
        float rx = rowx[i], ry = rowy[i];
#pragma unroll
        for (int off = 8; off > 0; off >>= 1) {
            rx += __shfl_down_sync(0xffffffffu, rx, off, 16);
            ry += __shfl_down_sync(0xffffffffu, ry, off, 16);
        }
        if (tx == 0) { sh_rsx[ty * 8 + i] = rx; sh_rsy[ty * 8 + i] = ry; }
    }
    // col sums: shared atomics (8-way across ty groups)
    __syncthreads();   // sh_cs zero-init + rs writes visible
#pragma unroll
    for (int j = 0; j < 4; ++j) {
        atomicAdd(&sh_csx[tx * 4 + j], colx[j]);
        atomicAdd(&sh_csy[tx * 4 + j], coly[j]);
    }

    // scalar products: block reduce
#pragma unroll
    for (int off = 16; off > 0; off >>= 1) {
        pxy += __shfl_down_sync(0xffffffffu, pxy, off);
        pxx += __shfl_down_sync(0xffffffffu, pxx, off);
        pyy += __shfl_down_sync(0xffffffffu, pyy, off);
    }
    if ((tid & 31) == 0) {
        sh_p[0][tid >> 5] = pxy; sh_p[1][tid >> 5] = pxx; sh_p[2][tid >> 5] = pyy;
    }
    __syncthreads();

    if (tid < 64) {
        atomicAdd(&g_rs[0][I + tid], sh_rsx[tid]);
        atomicAdd(&g_rs[1][I + tid], sh_rsy[tid]);
        if (!diag) {   // symmetric contribution to rows J..
            atomicAdd(&g_rs[0][J + tid], sh_csx[tid]);
            atomicAdd(&g_rs[1][J + tid], sh_csy[tid]);
        }
    }
    if (tid == 0) {
        const double scl = diag ? 1.0 : 2.0;
        atomicAdd(&g_acc[0], scl * (double)(sh_p[0][0] + sh_p[0][1] + sh_p[0][2] + sh_p[0][3]));
        atomicAdd(&g_acc[1], scl * (double)(sh_p[1][0] + sh_p[1][1] + sh_p[1][2] + sh_p[1][3]));
        atomicAdd(&g_acc[2], scl * (double)(sh_p[2][0] + sh_p[2][1] + sh_p[2][2] + sh_p[2][3]));
    }
}

// ---------------------------------------------------------------------------
// Kernel 3: finalize via the double-centering identity (all in double):
//  sum(a*b) = S_xy - (2/N) * sum_i Rx_i*Ry_i + Tx*Ty/N^2
// ---------------------------------------------------------------------------
__global__ void finalize_kernel(float* __restrict__ out) {
    const int t = threadIdx.x;   // 512 threads, 2 rows each
    double sRR = 0.0, sXX = 0.0, sYY = 0.0, sX = 0.0, sY = 0.0;
#pragma unroll
    for (int q = 0; q < 2; ++q) {
        const int i = t + q * 512;
        const double rx = (double)g_rs[0][i];
        const double ry = (double)g_rs[1][i];
        sRR += rx * ry; sXX += rx * rx; sYY += ry * ry; sX += rx; sY += ry;
    }
#pragma unroll
    for (int off = 16; off > 0; off >>= 1) {
        sRR += __shfl_down_sync(0xffffffffu, sRR, off);
        sXX += __shfl_down_sync(0xffffffffu, sXX, off);
        sYY += __shfl_down_sync(0xffffffffu, sYY, off);
        sX  += __shfl_down_sync(0xffffffffu, sX, off);
        sY  += __shfl_down_sync(0xffffffffu, sY, off);
    }
    __shared__ double sd[5][16];
    const int lane = t & 31, wid = t >> 5;
    if (lane == 0) { sd[0][wid] = sRR; sd[1][wid] = sXX; sd[2][wid] = sYY; sd[3][wid] = sX; sd[4][wid] = sY; }
    __syncthreads();
    if (t == 0) {
        double a0 = 0, a1 = 0, a2 = 0, a3 = 0, a4 = 0;
#pragma unroll
        for (int q = 0; q < 16; ++q) {
            a0 += sd[0][q]; a1 += sd[1][q]; a2 += sd[2][q]; a3 += sd[3][q]; a4 += sd[4][q];
        }
        const double N = (double)NPTS, N2 = N * N;
        const double sumab = g_acc[0] - (2.0 / N) * a0 + (a3 * a4) / N2;
        const double sumaa = g_acc[1] - (2.0 / N) * a1 + (a3 * a3) / N2;
        const double sumbb = g_acc[2] - (2.0 / N) * a2 + (a4 * a4) / N2;
        const double mxy = sumab / N2, mxx = sumaa / N2, myy = sumbb / N2;
        const double r = mxy / sqrt(mxx * myy + 1e-9);
        out[0] = (float)(1.0 - r);
    }
}

extern "C" void kernel_launch(void* const* d_in, const int* in_sizes, int n_in,
                              void* d_out, int out_size) {
    const float* a = (const float*)d_in[0];  // output_1 (1024,64,256) f32
    const float* b = (const float*)d_in[1];  // feature  (1024,64,256) f32
    // d_in[2] = mask, unused by the reference module.

    mean_norm_kernel<<<dim3(NPTS / 4, 2), 256>>>(a, b);
    gemm_dist_fused_kernel<<<NBLK, 128>>>();
    finalize_kernel<<<1, 512>>>((float*)d_out);
}